// round 9
// baseline (speedup 1.0000x reference)
#include <cuda_runtime.h>
#include <cstdint>

// ---------------------------------------------------------------------------
// CausalSelfAttentionWithBias: B=4, T=2048, C=1024, H=16, D=64
// tf32 mma.m16n8k8 (legacy path; tcgen05 rejected by harness ptxas target).
// GEMMs: R7 cp.async 2-stage. Attention: 128-row q-tiles, double-buffered K/V.
// ---------------------------------------------------------------------------

#define TT 2048
#define HH 16

__device__ float g_q[4 * HH * TT * 64];
__device__ float g_k[4 * HH * TT * 64];
__device__ float g_v[4 * HH * TT * 64];
__device__ float g_y[4 * TT * 1024];
__device__ float g_x[4 * TT * 1024];      // x rounded to tf32
__device__ float g_wa[1024 * 3072];       // W_attn rounded
__device__ float g_wp[1024 * 1024];       // W_proj rounded

__device__ __forceinline__ unsigned f2t(float x) {
    unsigned u; asm("cvt.rna.tf32.f32 %0, %1;" : "=r"(u) : "f"(x)); return u;
}
__device__ __forceinline__ void mma8(float* d, const unsigned* a, const unsigned* b) {
    asm volatile(
        "mma.sync.aligned.m16n8k8.row.col.f32.tf32.tf32.f32 "
        "{%0,%1,%2,%3}, {%4,%5,%6,%7}, {%8,%9}, {%0,%1,%2,%3};"
        : "+f"(d[0]), "+f"(d[1]), "+f"(d[2]), "+f"(d[3])
        : "r"(a[0]), "r"(a[1]), "r"(a[2]), "r"(a[3]), "r"(b[0]), "r"(b[1]));
}
__device__ __forceinline__ unsigned sptr(const void* p) {
    return (unsigned)__cvta_generic_to_shared(p);
}
__device__ __forceinline__ void ldsm4(unsigned* r, unsigned addr) {
    asm volatile("ldmatrix.sync.aligned.m8n8.x4.shared.b16 {%0,%1,%2,%3}, [%4];"
        : "=r"(r[0]), "=r"(r[1]), "=r"(r[2]), "=r"(r[3]) : "r"(addr));
}
__device__ __forceinline__ void cpa16(unsigned dst, const void* src) {
    asm volatile("cp.async.cg.shared.global [%0], [%1], 16;" :: "r"(dst), "l"(src));
}
__device__ __forceinline__ void cp_commit() {
    asm volatile("cp.async.commit_group;");
}
template <int N> __device__ __forceinline__ void cp_wait() {
    asm volatile("cp.async.wait_group %0;" :: "n"(N));
}

// ---------------------------------------------------------------------------
// Prepass: round fp32 -> tf32-valued fp32
// ---------------------------------------------------------------------------
__global__ void cvt_kernel(const float* __restrict__ src, float* __restrict__ dst, int n4)
{
    int i = blockIdx.x * blockDim.x + threadIdx.x;
    if (i < n4) {
        float4 v = ((const float4*)src)[i];
        v.x = __uint_as_float(f2t(v.x));
        v.y = __uint_as_float(f2t(v.y));
        v.z = __uint_as_float(f2t(v.z));
        v.w = __uint_as_float(f2t(v.w));
        ((float4*)dst)[i] = v;
    }
}

#define SA 20    // A smem row stride (words)
#define SB 136   // B smem (k-major) row stride (words)
#define A_STG (128 * SA)
#define B_STG (16 * SB)

// ---------------------------------------------------------------------------
// GEMM core (R7): 128x128 block, BK=16, 2-stage cp.async, 8 warps, 64x32 warp
// ---------------------------------------------------------------------------
#define GEMM_BODY(LDB_, Ag_, Bg_)                                               \
    __shared__ unsigned As[2 * A_STG];                                          \
    __shared__ unsigned Bs[2 * B_STG];                                          \
    const int tid = threadIdx.x;                                                \
    const int wid = tid >> 5, lane = tid & 31;                                  \
    const int mBase = (wid >> 2) * 64, nBase = (wid & 3) * 32;                  \
    const int g = lane >> 2, t = lane & 3;                                      \
    float acc[4][4][4] = {};                                                    \
    const unsigned sAs = sptr(As), sBs = sptr(Bs);                              \
    const int rA = (lane & 7) + ((lane >> 3) & 1) * 8;                          \
    const int kA = ((lane >> 4) & 1) * 4;                                       \
    const unsigned aOff = (mBase + rA) * SA + kA;                               \
    const int ar = tid >> 2, ac4 = tid & 3;                                     \
    const int bk = tid >> 5, bc = tid & 31;                                     \
    {                                                                           \
        cpa16(sAs + (ar * SA + ac4 * 4) * 4, Ag_ + (size_t)ar * 1024 + ac4 * 4);        \
        cpa16(sAs + ((ar + 64) * SA + ac4 * 4) * 4, Ag_ + (size_t)(ar + 64) * 1024 + ac4 * 4); \
        cpa16(sBs + (bk * SB + bc * 4) * 4, Bg_ + (size_t)bk * LDB_ + bc * 4);          \
        cpa16(sBs + ((bk + 8) * SB + bc * 4) * 4, Bg_ + (size_t)(bk + 8) * LDB_ + bc * 4); \
        cp_commit();                                                            \
    }                                                                           \
    for (int i = 0; i < 64; i++) {                                              \
        const int s = i & 1;                                                    \
        if (i + 1 < 64) {                                                       \
            const int kb = (i + 1) * 16;                                        \
            const int so = (s ^ 1);                                             \
            cpa16(sAs + (so * A_STG + ar * SA + ac4 * 4) * 4,                   \
                  Ag_ + (size_t)ar * 1024 + kb + ac4 * 4);                      \
            cpa16(sAs + (so * A_STG + (ar + 64) * SA + ac4 * 4) * 4,            \
                  Ag_ + (size_t)(ar + 64) * 1024 + kb + ac4 * 4);               \
            cpa16(sBs + (so * B_STG + bk * SB + bc * 4) * 4,                    \
                  Bg_ + (size_t)(kb + bk) * LDB_ + bc * 4);                     \
            cpa16(sBs + (so * B_STG + (bk + 8) * SB + bc * 4) * 4,              \
                  Bg_ + (size_t)(kb + bk + 8) * LDB_ + bc * 4);                 \
            cp_commit();                                                        \
            cp_wait<1>();                                                       \
        } else {                                                                \
            cp_wait<0>();                                                       \
        }                                                                       \
        __syncthreads();                                                        \
        const unsigned aS = sAs + s * A_STG * 4;                                \
        const unsigned* BsS = Bs + s * B_STG;                                   \
        _Pragma("unroll")                                                       \
        for (int kk = 0; kk < 2; kk++) {                                        \
            const int k0 = kk * 8;                                              \
            unsigned af[4][4], bf[4][2];                                        \
            _Pragma("unroll")                                                   \
            for (int ii = 0; ii < 4; ii++)                                      \
                ldsm4(af[ii], aS + (aOff + ii * 16 * SA + k0) * 4);             \
            _Pragma("unroll")                                                   \
            for (int j = 0; j < 4; j++) {                                       \
                const int c0 = nBase + j * 8 + g;                               \
                bf[j][0] = BsS[(k0 + t) * SB + c0];                             \
                bf[j][1] = BsS[(k0 + t + 4) * SB + c0];                         \
            }                                                                   \
            _Pragma("unroll")                                                   \
            for (int ii = 0; ii < 4; ii++)                                      \
                _Pragma("unroll")                                               \
                for (int j = 0; j < 4; j++)                                     \
                    mma8(acc[ii][j], af[ii], bf[j]);                            \
        }                                                                       \
        __syncthreads();                                                        \
    }

// ---------------------------------------------------------------------------
// Stage 1: QKV GEMM (M=8192, K=1024, N=3072)
// ---------------------------------------------------------------------------
__global__ __launch_bounds__(256, 2)
void gemm_qkv_kernel(const float* __restrict__ b_attn,
                     const float* __restrict__ bQ,
                     const float* __restrict__ bK,
                     const float* __restrict__ bV)
{
    const int cRow = blockIdx.y, cCol = blockIdx.x;
    const float* Ag = g_x + (size_t)cRow * 128 * 1024;
    const float* Bg = g_wa + cCol * 128;

    GEMM_BODY(3072, Ag, Bg)

    const int colW  = cCol * 128 + nBase;
    const int which = colW >> 10;
    const int h     = (colW & 1023) >> 6;
    float* dstBase  = which == 0 ? g_q : (which == 1 ? g_k : g_v);
    const float* hb = (which == 0 ? bQ : (which == 1 ? bK : bV)) + h * 64;
    const float scale = (which == 0) ? 0.125f : 1.0f;

    #pragma unroll
    for (int j = 0; j < 4; j++) {
        int col = colW + j * 8 + t * 2;
        int d0 = col & 63;
        float bb0 = (b_attn[col]     + hb[d0])     * scale;
        float bb1 = (b_attn[col + 1] + hb[d0 + 1]) * scale;
        #pragma unroll
        for (int ii = 0; ii < 4; ii++) {
            int row0 = cRow * 128 + mBase + ii * 16 + g;
            #pragma unroll
            for (int rh = 0; rh < 2; rh++) {
                int row = row0 + rh * 8;
                int b = row >> 11, tt_ = row & 2047;
                float2 o;
                o.x = __uint_as_float(f2t(acc[ii][j][rh * 2 + 0] * scale + bb0));
                o.y = __uint_as_float(f2t(acc[ii][j][rh * 2 + 1] * scale + bb1));
                *(float2*)(dstBase + (((size_t)(b * HH + h) * TT + tt_) << 6) + d0) = o;
            }
        }
    }
}

// ---------------------------------------------------------------------------
// Stage 2: causal flash attention. 128-row q-tiles, 8 warps (256 thr),
// double-buffered K/V (cp.async prefetch 1 tile ahead), dedicated P buffer.
// ---------------------------------------------------------------------------
#define SQ 68
#define SV 72
#define KST (64 * SQ)            // words per K stage
#define VST (64 * SV)            // words per V stage
#define ATT_SMEM ((2 * KST + 2 * VST + 8 * 16 * SQ) * 4)   // 106496 bytes

__global__ __launch_bounds__(256, 2)
void attn_kernel()
{
    extern __shared__ unsigned smA[];
    unsigned* Vst0 = smA + 2 * KST;
    unsigned* Pb   = smA + 2 * KST + 2 * VST;

    const int tid = threadIdx.x;
    const int w = tid >> 5, lane = tid & 31;
    const int g = lane >> 2, t = lane & 3;
    const int bh = blockIdx.y;
    const int qt = 15 - blockIdx.x;       // longest CTAs first
    const int q0 = qt * 128;

    const float* kbase = g_k + (size_t)bh * TT * 64;
    const float* vbase = g_v + (size_t)bh * TT * 64;

    // Q fragments (pre-scaled, tf32-valued): warp owns q rows q0+w*16..+15
    unsigned qa[8][4];
    {
        const float* q0p = g_q + (size_t)bh * TT * 64 + (size_t)(q0 + w * 16 + g) * 64;
        const float* q1p = q0p + 8 * 64;
        #pragma unroll
        for (int kk = 0; kk < 8; kk++) {
            qa[kk][0] = __float_as_uint(q0p[kk * 8 + t]);
            qa[kk][1] = __float_as_uint(q1p[kk * 8 + t]);
            qa[kk][2] = __float_as_uint(q0p[kk * 8 + t + 4]);
            qa[kk][3] = __float_as_uint(q1p[kk * 8 + t + 4]);
        }
    }

    float oacc[8][4] = {};
    float mrow[2] = {-1e30f, -1e30f};
    float lrow[2] = {0.f, 0.f};

    unsigned* Psw = Pb + w * 16 * SQ;
    const unsigned sK0 = sptr(smA), sK1 = sK0 + KST * 4;
    const unsigned sV0 = sptr(Vst0), sV1 = sV0 + VST * 4;

    const int rBf = (lane & 7) + ((lane >> 4) & 1) * 8;
    const int kBf = ((lane >> 3) & 1) * 4;
    const int rAf = (lane & 7) + ((lane >> 3) & 1) * 8;
    const int kAf = ((lane >> 4) & 1) * 4;
    const unsigned pAddr = sptr(Psw) + (rAf * SQ + kAf) * 4;

    const int fr = tid >> 4, fc4 = (tid & 15) * 4;   // fill: 4 rounds of 64x16 f4

    #define ATT_FILL(tile, dK, dV)                                              \
        {                                                                       \
            const float* kt_ = kbase + (size_t)(tile) * 64 * 64;                \
            const float* vt_ = vbase + (size_t)(tile) * 64 * 64;                \
            _Pragma("unroll")                                                   \
            for (int i_ = 0; i_ < 4; i_++) {                                    \
                int r_ = fr + i_ * 16;                                          \
                cpa16((dK) + (r_ * SQ + fc4) * 4, kt_ + r_ * 64 + fc4);         \
                cpa16((dV) + (r_ * SV + fc4) * 4, vt_ + r_ * 64 + fc4);         \
            }                                                                   \
        }

    const int tmax = 2 * qt + 1;
    ATT_FILL(0, sK0, sV0)
    cp_commit();

    for (int tI = 0; tI <= tmax; tI++) {
        const int s = tI & 1;
        const unsigned sKs = s ? sK1 : sK0;
        const unsigned* Vs = Vst0 + (s ? VST : 0);

        __syncthreads();                 // stage s^1 readers (tile tI-1) done
        if (tI < tmax) {
            ATT_FILL(tI + 1, s ? sK0 : sK1, s ? sV0 : sV1)
            cp_commit();
            cp_wait<1>();
        } else {
            cp_wait<0>();
        }
        __syncthreads();

        // S = Q . K^T  (16 x 64 per warp)
        const unsigned kAddr = sKs + (rBf * SQ + kBf) * 4;
        float sacc[8][4] = {};
        #pragma unroll
        for (int kk = 0; kk < 8; kk++) {
            const int k0 = kk * 8;
            #pragma unroll
            for (int jp = 0; jp < 4; jp++) {
                unsigned kf[4];
                ldsm4(kf, kAddr + (jp * 16 * SQ + k0) * 4);
                mma8(sacc[jp * 2 + 0], qa[kk], &kf[0]);
                mma8(sacc[jp * 2 + 1], qa[kk], &kf[2]);
            }
        }

        // causal mask (global coords); warp-uniform trigger
        const int wrow = q0 + w * 16;
        if (tI * 64 + 63 > wrow) {
            #pragma unroll
            for (int j = 0; j < 8; j++)
                #pragma unroll
                for (int r = 0; r < 4; r++) {
                    int rq = wrow + g + (r >> 1) * 8;
                    int cq = tI * 64 + j * 8 + t * 2 + (r & 1);
                    if (cq > rq) sacc[j][r] = -1e30f;
                }
        }

        // online softmax
        float corr[2];
        #pragma unroll
        for (int rh = 0; rh < 2; rh++) {
            float mt = -1e30f;
            #pragma unroll
            for (int j = 0; j < 8; j++)
                mt = fmaxf(mt, fmaxf(sacc[j][rh * 2], sacc[j][rh * 2 + 1]));
            mt = fmaxf(mt, __shfl_xor_sync(0xffffffffu, mt, 1));
            mt = fmaxf(mt, __shfl_xor_sync(0xffffffffu, mt, 2));
            float mn = fmaxf(mrow[rh], mt);
            corr[rh] = __expf(mrow[rh] - mn);
            mrow[rh] = mn;
        }
        float ls0 = 0.f, ls1 = 0.f;
        #pragma unroll
        for (int j = 0; j < 8; j++) {
            float p0 = __expf(sacc[j][0] - mrow[0]);
            float p1 = __expf(sacc[j][1] - mrow[0]);
            float p2 = __expf(sacc[j][2] - mrow[1]);
            float p3 = __expf(sacc[j][3] - mrow[1]);
            sacc[j][0] = p0; sacc[j][1] = p1; sacc[j][2] = p2; sacc[j][3] = p3;
            ls0 += p0 + p1; ls1 += p2 + p3;
        }
        ls0 += __shfl_xor_sync(0xffffffffu, ls0, 1);
        ls0 += __shfl_xor_sync(0xffffffffu, ls0, 2);
        ls1 += __shfl_xor_sync(0xffffffffu, ls1, 1);
        ls1 += __shfl_xor_sync(0xffffffffu, ls1, 2);
        lrow[0] = lrow[0] * corr[0] + ls0;
        lrow[1] = lrow[1] * corr[1] + ls1;

        #pragma unroll
        for (int j = 0; j < 8; j++) {
            oacc[j][0] *= corr[0]; oacc[j][1] *= corr[0];
            oacc[j][2] *= corr[1]; oacc[j][3] *= corr[1];
        }

        // P -> dedicated per-warp smem (tf32); no cross-warp hazard
        #pragma unroll
        for (int j = 0; j < 8; j++) {
            unsigned* p0 = &Psw[g * SQ + j * 8 + t * 2];
            p0[0] = f2t(sacc[j][0]); p0[1] = f2t(sacc[j][1]);
            unsigned* p1 = &Psw[(g + 8) * SQ + j * 8 + t * 2];
            p1[0] = f2t(sacc[j][2]); p1[1] = f2t(sacc[j][3]);
        }
        __syncwarp();

        // O += P . V
        #pragma unroll
        for (int kk = 0; kk < 8; kk++) {
            const int k0 = kk * 8;
            unsigned pa[4];
            ldsm4(pa, pAddr + k0 * 4);
            #pragma unroll
            for (int j = 0; j < 8; j++) {
                unsigned vb[2];
                vb[0] = Vs[(k0 + t) * SV + j * 8 + g];
                vb[1] = Vs[(k0 + t + 4) * SV + j * 8 + g];
                mma8(oacc[j], pa, vb);
            }
        }
    }
    #undef ATT_FILL

    // write y [B,T,C], tf32-rounded (proj consumes directly)
    const int b = bh >> 4, h = bh & 15;
    const float inv0 = 1.f / lrow[0], inv1 = 1.f / lrow[1];
    float* yb = g_y + ((size_t)b * TT + q0 + w * 16) * 1024 + h * 64;
    #pragma unroll
    for (int j = 0; j < 8; j++) {
        float2 o0, o1;
        o0.x = __uint_as_float(f2t(oacc[j][0] * inv0));
        o0.y = __uint_as_float(f2t(oacc[j][1] * inv0));
        o1.x = __uint_as_float(f2t(oacc[j][2] * inv1));
        o1.y = __uint_as_float(f2t(oacc[j][3] * inv1));
        *(float2*)(yb + (size_t)g * 1024 + j * 8 + t * 2) = o0;
        *(float2*)(yb + (size_t)(g + 8) * 1024 + j * 8 + t * 2) = o1;
    }
}

// ---------------------------------------------------------------------------
// Stage 3: out = y @ W_proj + b_proj  (M=8192, K=1024, N=1024)
// ---------------------------------------------------------------------------
__global__ __launch_bounds__(256, 2)
void gemm_proj_kernel(const float* __restrict__ b_proj,
                      float* __restrict__ out)
{
    const int cRow = blockIdx.y, cCol = blockIdx.x;
    const float* Ag = g_y + (size_t)cRow * 128 * 1024;
    const float* Bg = g_wp + cCol * 128;

    GEMM_BODY(1024, Ag, Bg)

    #pragma unroll
    for (int j = 0; j < 4; j++) {
        int col = cCol * 128 + nBase + j * 8 + t * 2;
        float bb0 = b_proj[col], bb1 = b_proj[col + 1];
        #pragma unroll
        for (int ii = 0; ii < 4; ii++) {
            int row0 = cRow * 128 + mBase + ii * 16 + g;
            #pragma unroll
            for (int rh = 0; rh < 2; rh++) {
                int row = row0 + rh * 8;
                float2 o;
                o.x = acc[ii][j][rh * 2 + 0] + bb0;
                o.y = acc[ii][j][rh * 2 + 1] + bb1;
                *(float2*)(out + (size_t)row * 1024 + col) = o;
            }
        }
    }
}

// ---------------------------------------------------------------------------
extern "C" void kernel_launch(void* const* d_in, const int* in_sizes, int n_in,
                              void* d_out, int out_size)
{
    (void)in_sizes; (void)n_in; (void)out_size;
    const float* x      = (const float*)d_in[0];
    const float* W_attn = (const float*)d_in[1];
    const float* b_attn = (const float*)d_in[2];
    const float* W_proj = (const float*)d_in[3];
    const float* b_proj = (const float*)d_in[4];
    const float* bQ     = (const float*)d_in[5];
    const float* bK     = (const float*)d_in[6];
    const float* bV     = (const float*)d_in[7];
    float* out = (float*)d_out;

    cudaFuncSetAttribute(attn_kernel,
                         cudaFuncAttributeMaxDynamicSharedMemorySize, ATT_SMEM);

    float *p_x, *p_wa, *p_wp;
    cudaGetSymbolAddress((void**)&p_x,  g_x);
    cudaGetSymbolAddress((void**)&p_wa, g_wa);
    cudaGetSymbolAddress((void**)&p_wp, g_wp);

    // prepass: round inputs to tf32 (once)
    cvt_kernel<<<(2097152 + 255) / 256, 256>>>(x,      p_x,  2097152);
    cvt_kernel<<<(786432  + 255) / 256, 256>>>(W_attn, p_wa, 786432);
    cvt_kernel<<<(262144  + 255) / 256, 256>>>(W_proj, p_wp, 262144);

    dim3 g1(24, 64);
    gemm_qkv_kernel<<<g1, 256>>>(b_attn, bQ, bK, bV);

    dim3 ga(16, 4 * HH);           // 2048/128 q-tiles x 64 heads
    attn_kernel<<<ga, 256, ATT_SMEM>>>();

    dim3 g2(8, 64);
    gemm_proj_kernel<<<g2, 256>>>(b_proj, out);
}

// round 10
// speedup vs baseline: 1.1349x; 1.1349x over previous
#include <cuda_runtime.h>
#include <cstdint>

// ---------------------------------------------------------------------------
// CausalSelfAttentionWithBias: B=4, T=2048, C=1024, H=16, D=64
// tf32 mma.m16n8k8. GEMMs: BK=32, cp.async 2-stage, transposed-B (n-major),
// all fragments via ldmatrix. Attention: R7 64-row flash (proven best).
// ---------------------------------------------------------------------------

#define TT 2048
#define HH 16

__device__ float g_q[4 * HH * TT * 64];
__device__ float g_k[4 * HH * TT * 64];
__device__ float g_v[4 * HH * TT * 64];
__device__ float g_y[4 * TT * 1024];
__device__ float g_x[4 * TT * 1024];      // x rounded to tf32
__device__ float g_wa[3072 * 1024];       // W_attn^T [n][k], tf32-rounded
__device__ float g_wp[1024 * 1024];       // W_proj^T [n][k], tf32-rounded

__device__ __forceinline__ unsigned f2t(float x) {
    unsigned u; asm("cvt.rna.tf32.f32 %0, %1;" : "=r"(u) : "f"(x)); return u;
}
__device__ __forceinline__ void mma8(float* d, const unsigned* a, const unsigned* b) {
    asm volatile(
        "mma.sync.aligned.m16n8k8.row.col.f32.tf32.tf32.f32 "
        "{%0,%1,%2,%3}, {%4,%5,%6,%7}, {%8,%9}, {%0,%1,%2,%3};"
        : "+f"(d[0]), "+f"(d[1]), "+f"(d[2]), "+f"(d[3])
        : "r"(a[0]), "r"(a[1]), "r"(a[2]), "r"(a[3]), "r"(b[0]), "r"(b[1]));
}
__device__ __forceinline__ unsigned sptr(const void* p) {
    return (unsigned)__cvta_generic_to_shared(p);
}
__device__ __forceinline__ void ldsm4(unsigned* r, unsigned addr) {
    asm volatile("ldmatrix.sync.aligned.m8n8.x4.shared.b16 {%0,%1,%2,%3}, [%4];"
        : "=r"(r[0]), "=r"(r[1]), "=r"(r[2]), "=r"(r[3]) : "r"(addr));
}
__device__ __forceinline__ void cpa16(unsigned dst, const void* src) {
    asm volatile("cp.async.cg.shared.global [%0], [%1], 16;" :: "r"(dst), "l"(src));
}
__device__ __forceinline__ void cp_commit() {
    asm volatile("cp.async.commit_group;");
}
template <int N> __device__ __forceinline__ void cp_wait() {
    asm volatile("cp.async.wait_group %0;" :: "n"(N));
}

// ---------------------------------------------------------------------------
// Prepasses
// ---------------------------------------------------------------------------
__global__ void cvt_kernel(const float* __restrict__ src, float* __restrict__ dst, int n4)
{
    int i = blockIdx.x * blockDim.x + threadIdx.x;
    if (i < n4) {
        float4 v = ((const float4*)src)[i];
        v.x = __uint_as_float(f2t(v.x));
        v.y = __uint_as_float(f2t(v.y));
        v.z = __uint_as_float(f2t(v.z));
        v.w = __uint_as_float(f2t(v.w));
        ((float4*)dst)[i] = v;
    }
}

// src [K][N] row-major -> dst [N][K] row-major, tf32-rounded
__global__ void transpose_cvt(const float* __restrict__ src, float* __restrict__ dst,
                              int K, int N)
{
    __shared__ float tile[32][33];
    const int n0 = blockIdx.x * 32, k0 = blockIdx.y * 32;
    const int tx = threadIdx.x, ty = threadIdx.y;
    #pragma unroll
    for (int j = 0; j < 4; j++)
        tile[ty + j * 8][tx] = src[(size_t)(k0 + ty + j * 8) * N + n0 + tx];
    __syncthreads();
    #pragma unroll
    for (int j = 0; j < 4; j++)
        dst[(size_t)(n0 + ty + j * 8) * K + k0 + tx] =
            __uint_as_float(f2t(tile[tx][ty + j * 8]));
}

#define SA 36                 // smem row stride (words) for 32-k rows
#define A_STG (128 * SA)      // words per stage (A and B identical: 128 x 32)
#define GSMEM (4 * A_STG * 4) // 2 stages A + 2 stages B, bytes = 73728

// ---------------------------------------------------------------------------
// GEMM core: 128x128 CTA tile, BK=32, 2-stage cp.async, 8 warps (2x4),
// warp tile 64x32, A and B fragments both via ldmatrix (B n-major).
// ---------------------------------------------------------------------------
#define GEMM_BODY(Ag_, Bg_)                                                     \
    extern __shared__ unsigned dynsm_g[];                                       \
    unsigned* As = dynsm_g;                                                     \
    unsigned* Bs = dynsm_g + 2 * A_STG;                                         \
    const int tid = threadIdx.x;                                                \
    const int wid = tid >> 5, lane = tid & 31;                                  \
    const int mBase = (wid >> 2) * 64, nBase = (wid & 3) * 32;                  \
    const int g = lane >> 2, t = lane & 3;                                      \
    float acc[4][4][4] = {};                                                    \
    const unsigned sAs = sptr(As), sBs = sptr(Bs);                              \
    const int rA = (lane & 7) + ((lane >> 3) & 1) * 8;                          \
    const int kA = ((lane >> 4) & 1) * 4;                                       \
    const unsigned aOff = (mBase + rA) * SA + kA;                               \
    const int rB = (lane & 7) + ((lane >> 4) & 1) * 8;                          \
    const int kB = ((lane >> 3) & 1) * 4;                                       \
    const unsigned bOff = (nBase + rB) * SA + kB;                               \
    const int fr = tid >> 1;                         /* unused helper */        \
    (void)fr;                                                                   \
    /* fill: 128x32 = 1024 f4 chunks per operand; 4 per thread */               \
    {                                                                           \
        _Pragma("unroll") for (int j = 0; j < 4; j++) {                         \
            int id = tid + j * 256, r = id >> 3, c4 = id & 7;                   \
            cpa16(sAs + (r * SA + c4 * 4) * 4, Ag_ + (size_t)r * 1024 + c4 * 4);\
            cpa16(sBs + (r * SA + c4 * 4) * 4, Bg_ + (size_t)r * 1024 + c4 * 4);\
        }                                                                       \
        cp_commit();                                                            \
    }                                                                           \
    for (int i = 0; i < 32; i++) {                                              \
        const int s = i & 1;                                                    \
        if (i + 1 < 32) {                                                       \
            const int kb = (i + 1) * 32;                                        \
            const unsigned so = (unsigned)(s ^ 1) * A_STG * 4;                  \
            _Pragma("unroll") for (int j = 0; j < 4; j++) {                     \
                int id = tid + j * 256, r = id >> 3, c4 = id & 7;               \
                cpa16(sAs + so + (r * SA + c4 * 4) * 4,                         \
                      Ag_ + (size_t)r * 1024 + kb + c4 * 4);                    \
                cpa16(sBs + so + (r * SA + c4 * 4) * 4,                         \
                      Bg_ + (size_t)r * 1024 + kb + c4 * 4);                    \
            }                                                                   \
            cp_commit();                                                        \
            cp_wait<1>();                                                       \
        } else {                                                                \
            cp_wait<0>();                                                       \
        }                                                                       \
        __syncthreads();                                                        \
        const unsigned aS = sAs + (unsigned)s * A_STG * 4;                      \
        const unsigned bS = sBs + (unsigned)s * A_STG * 4;                      \
        _Pragma("unroll")                                                       \
        for (int kk = 0; kk < 4; kk++) {                                        \
            const int k0 = kk * 8;                                              \
            unsigned af[4][4], bf[2][4];                                        \
            _Pragma("unroll")                                                   \
            for (int ii = 0; ii < 4; ii++)                                      \
                ldsm4(af[ii], aS + (aOff + ii * 16 * SA + k0) * 4);             \
            _Pragma("unroll")                                                   \
            for (int jp = 0; jp < 2; jp++)                                      \
                ldsm4(bf[jp], bS + (bOff + jp * 16 * SA + k0) * 4);             \
            _Pragma("unroll")                                                   \
            for (int ii = 0; ii < 4; ii++)                                      \
                _Pragma("unroll")                                               \
                for (int j = 0; j < 4; j++)                                     \
                    mma8(acc[ii][j], af[ii], &bf[j >> 1][(j & 1) * 2]);         \
        }                                                                       \
        __syncthreads();                                                        \
    }

// ---------------------------------------------------------------------------
// Stage 1: QKV GEMM (M=8192, K=1024, N=3072). grid (24, 64)
// ---------------------------------------------------------------------------
__global__ __launch_bounds__(256, 2)
void gemm_qkv_kernel(const float* __restrict__ b_attn,
                     const float* __restrict__ bQ,
                     const float* __restrict__ bK,
                     const float* __restrict__ bV)
{
    const int cRow = blockIdx.y, cCol = blockIdx.x;
    const float* Ag = g_x + (size_t)cRow * 128 * 1024;
    const float* Bg = g_wa + (size_t)cCol * 128 * 1024;

    GEMM_BODY(Ag, Bg)

    const int colW  = cCol * 128 + nBase;
    const int which = colW >> 10;
    const int h     = (colW & 1023) >> 6;
    float* dstBase  = which == 0 ? g_q : (which == 1 ? g_k : g_v);
    const float* hb = (which == 0 ? bQ : (which == 1 ? bK : bV)) + h * 64;
    const float scale = (which == 0) ? 0.125f : 1.0f;

    #pragma unroll
    for (int j = 0; j < 4; j++) {
        int col = colW + j * 8 + t * 2;
        int d0 = col & 63;
        float bb0 = (b_attn[col]     + hb[d0])     * scale;
        float bb1 = (b_attn[col + 1] + hb[d0 + 1]) * scale;
        #pragma unroll
        for (int ii = 0; ii < 4; ii++) {
            int row0 = cRow * 128 + mBase + ii * 16 + g;
            #pragma unroll
            for (int rh = 0; rh < 2; rh++) {
                int row = row0 + rh * 8;
                int b = row >> 11, tt_ = row & 2047;
                float2 o;
                o.x = __uint_as_float(f2t(acc[ii][j][rh * 2 + 0] * scale + bb0));
                o.y = __uint_as_float(f2t(acc[ii][j][rh * 2 + 1] * scale + bb1));
                *(float2*)(dstBase + (((size_t)(b * HH + h) * TT + tt_) << 6) + d0) = o;
            }
        }
    }
}

// ---------------------------------------------------------------------------
// Stage 3: proj GEMM (M=8192, K=1024, N=1024). grid (8, 64)
// ---------------------------------------------------------------------------
__global__ __launch_bounds__(256, 2)
void gemm_proj_kernel(const float* __restrict__ b_proj,
                      float* __restrict__ out)
{
    const int cRow = blockIdx.y, cCol = blockIdx.x;
    const float* Ag = g_y + (size_t)cRow * 128 * 1024;
    const float* Bg = g_wp + (size_t)cCol * 128 * 1024;

    GEMM_BODY(Ag, Bg)

    #pragma unroll
    for (int j = 0; j < 4; j++) {
        int col = cCol * 128 + nBase + j * 8 + t * 2;
        float bb0 = b_proj[col], bb1 = b_proj[col + 1];
        #pragma unroll
        for (int ii = 0; ii < 4; ii++) {
            int row0 = cRow * 128 + mBase + ii * 16 + g;
            #pragma unroll
            for (int rh = 0; rh < 2; rh++) {
                int row = row0 + rh * 8;
                float2 o;
                o.x = acc[ii][j][rh * 2 + 0] + bb0;
                o.y = acc[ii][j][rh * 2 + 1] + bb1;
                *(float2*)(out + (size_t)row * 1024 + col) = o;
            }
        }
    }
}

// ---------------------------------------------------------------------------
// Stage 2: causal flash attention (R7 version — proven best)
// ---------------------------------------------------------------------------
#define SQ 68
#define SV 72

__global__ __launch_bounds__(128)
void attn_kernel()
{
    __shared__ unsigned Ks[64 * SQ];
    __shared__ unsigned Vs[64 * SV];

    const int tid = threadIdx.x;
    const int w = tid >> 5, lane = tid & 31;
    const int g = lane >> 2, t = lane & 3;
    const int bh = blockIdx.y, qt = blockIdx.x;
    const int q0 = qt * 64;

    const float* qbase = g_q + (size_t)bh * TT * 64;
    const float* kbase = g_k + (size_t)bh * TT * 64;
    const float* vbase = g_v + (size_t)bh * TT * 64;

    unsigned qa[8][4];
    {
        const float* q0p = qbase + (size_t)(q0 + w * 16 + g) * 64;
        const float* q1p = q0p + 8 * 64;
        #pragma unroll
        for (int kk = 0; kk < 8; kk++) {
            qa[kk][0] = __float_as_uint(q0p[kk * 8 + t]);
            qa[kk][1] = __float_as_uint(q1p[kk * 8 + t]);
            qa[kk][2] = __float_as_uint(q0p[kk * 8 + t + 4]);
            qa[kk][3] = __float_as_uint(q1p[kk * 8 + t + 4]);
        }
    }

    float oacc[8][4] = {};
    float mrow[2] = {-1e30f, -1e30f};
    float lrow[2] = {0.f, 0.f};

    unsigned* Psw = Ks + w * 16 * SQ;
    const unsigned sKs = sptr(Ks), sVs = sptr(Vs);

    const int rBf = (lane & 7) + ((lane >> 4) & 1) * 8;
    const int kBf = ((lane >> 3) & 1) * 4;
    const unsigned kAddr = sKs + (rBf * SQ + kBf) * 4;
    const int rAf = (lane & 7) + ((lane >> 3) & 1) * 8;
    const int kAf = ((lane >> 4) & 1) * 4;
    const unsigned pAddr = sptr(Psw) + (rAf * SQ + kAf) * 4;

    for (int tI = 0; tI <= qt; tI++) {
        __syncthreads();
        const float* kt = kbase + (size_t)tI * 64 * 64;
        const float* vt = vbase + (size_t)tI * 64 * 64;
        #pragma unroll
        for (int i = 0; i < 8; i++) {
            int id = tid + i * 128;
            int r = id >> 4, c4 = id & 15;
            cpa16(sKs + (r * SQ + c4 * 4) * 4, kt + r * 64 + c4 * 4);
            cpa16(sVs + (r * SV + c4 * 4) * 4, vt + r * 64 + c4 * 4);
        }
        cp_commit();
        cp_wait<0>();
        __syncthreads();

        float sacc[8][4] = {};
        #pragma unroll
        for (int kk = 0; kk < 8; kk++) {
            const int k0 = kk * 8;
            #pragma unroll
            for (int jp = 0; jp < 4; jp++) {
                unsigned kf[4];
                ldsm4(kf, kAddr + (jp * 16 * SQ + k0) * 4);
                mma8(sacc[jp * 2 + 0], qa[kk], &kf[0]);
                mma8(sacc[jp * 2 + 1], qa[kk], &kf[2]);
            }
        }
        __syncthreads();

        if (tI == qt) {
            #pragma unroll
            for (int j = 0; j < 8; j++)
                #pragma unroll
                for (int r = 0; r < 4; r++) {
                    int rq = w * 16 + g + (r >> 1) * 8;
                    int cq = j * 8 + t * 2 + (r & 1);
                    if (cq > rq) sacc[j][r] = -1e30f;
                }
        }

        float corr[2];
        #pragma unroll
        for (int rh = 0; rh < 2; rh++) {
            float mt = -1e30f;
            #pragma unroll
            for (int j = 0; j < 8; j++)
                mt = fmaxf(mt, fmaxf(sacc[j][rh * 2], sacc[j][rh * 2 + 1]));
            mt = fmaxf(mt, __shfl_xor_sync(0xffffffffu, mt, 1));
            mt = fmaxf(mt, __shfl_xor_sync(0xffffffffu, mt, 2));
            float mn = fmaxf(mrow[rh], mt);
            corr[rh] = __expf(mrow[rh] - mn);
            mrow[rh] = mn;
        }
        float ls0 = 0.f, ls1 = 0.f;
        #pragma unroll
        for (int j = 0; j < 8; j++) {
            float p0 = __expf(sacc[j][0] - mrow[0]);
            float p1 = __expf(sacc[j][1] - mrow[0]);
            float p2 = __expf(sacc[j][2] - mrow[1]);
            float p3 = __expf(sacc[j][3] - mrow[1]);
            sacc[j][0] = p0; sacc[j][1] = p1; sacc[j][2] = p2; sacc[j][3] = p3;
            ls0 += p0 + p1; ls1 += p2 + p3;
        }
        ls0 += __shfl_xor_sync(0xffffffffu, ls0, 1);
        ls0 += __shfl_xor_sync(0xffffffffu, ls0, 2);
        ls1 += __shfl_xor_sync(0xffffffffu, ls1, 1);
        ls1 += __shfl_xor_sync(0xffffffffu, ls1, 2);
        lrow[0] = lrow[0] * corr[0] + ls0;
        lrow[1] = lrow[1] * corr[1] + ls1;

        #pragma unroll
        for (int j = 0; j < 8; j++) {
            oacc[j][0] *= corr[0]; oacc[j][1] *= corr[0];
            oacc[j][2] *= corr[1]; oacc[j][3] *= corr[1];
        }

        #pragma unroll
        for (int j = 0; j < 8; j++) {
            unsigned* p0 = &Psw[g * SQ + j * 8 + t * 2];
            p0[0] = f2t(sacc[j][0]); p0[1] = f2t(sacc[j][1]);
            unsigned* p1 = &Psw[(g + 8) * SQ + j * 8 + t * 2];
            p1[0] = f2t(sacc[j][2]); p1[1] = f2t(sacc[j][3]);
        }
        __syncwarp();

        #pragma unroll
        for (int kk = 0; kk < 8; kk++) {
            const int k0 = kk * 8;
            unsigned pa[4];
            ldsm4(pa, pAddr + k0 * 4);
            #pragma unroll
            for (int j = 0; j < 8; j++) {
                unsigned vb[2];
                vb[0] = Vs[(k0 + t) * SV + j * 8 + g];
                vb[1] = Vs[(k0 + t + 4) * SV + j * 8 + g];
                mma8(oacc[j], pa, vb);
            }
        }
    }

    const int b = bh >> 4, h = bh & 15;
    const float inv0 = 1.f / lrow[0], inv1 = 1.f / lrow[1];
    float* yb = g_y + ((size_t)b * TT + q0 + w * 16) * 1024 + h * 64;
    #pragma unroll
    for (int j = 0; j < 8; j++) {
        float2 o0, o1;
        o0.x = __uint_as_float(f2t(oacc[j][0] * inv0));
        o0.y = __uint_as_float(f2t(oacc[j][1] * inv0));
        o1.x = __uint_as_float(f2t(oacc[j][2] * inv1));
        o1.y = __uint_as_float(f2t(oacc[j][3] * inv1));
        *(float2*)(yb + (size_t)g * 1024 + j * 8 + t * 2) = o0;
        *(float2*)(yb + (size_t)(g + 8) * 1024 + j * 8 + t * 2) = o1;
    }
}

// ---------------------------------------------------------------------------
extern "C" void kernel_launch(void* const* d_in, const int* in_sizes, int n_in,
                              void* d_out, int out_size)
{
    (void)in_sizes; (void)n_in; (void)out_size;
    const float* x      = (const float*)d_in[0];
    const float* W_attn = (const float*)d_in[1];
    const float* b_attn = (const float*)d_in[2];
    const float* W_proj = (const float*)d_in[3];
    const float* b_proj = (const float*)d_in[4];
    const float* bQ     = (const float*)d_in[5];
    const float* bK     = (const float*)d_in[6];
    const float* bV     = (const float*)d_in[7];
    float* out = (float*)d_out;

    cudaFuncSetAttribute(gemm_qkv_kernel,
                         cudaFuncAttributeMaxDynamicSharedMemorySize, GSMEM);
    cudaFuncSetAttribute(gemm_proj_kernel,
                         cudaFuncAttributeMaxDynamicSharedMemorySize, GSMEM);

    float *p_x, *p_wa, *p_wp;
    cudaGetSymbolAddress((void**)&p_x,  g_x);
    cudaGetSymbolAddress((void**)&p_wa, g_wa);
    cudaGetSymbolAddress((void**)&p_wp, g_wp);

    // prepass: round x; transpose+round weights
    cvt_kernel<<<(2097152 + 255) / 256, 256>>>(x, p_x, 2097152);
    transpose_cvt<<<dim3(96, 32), dim3(32, 8)>>>(W_attn, p_wa, 1024, 3072);
    transpose_cvt<<<dim3(32, 32), dim3(32, 8)>>>(W_proj, p_wp, 1024, 1024);

    gemm_qkv_kernel<<<dim3(24, 64), 256, GSMEM>>>(b_attn, bQ, bK, bV);

    attn_kernel<<<dim3(TT / 64, 4 * HH), 128>>>();

    gemm_proj_kernel<<<dim3(8, 64), 256, GSMEM>>>(b_proj, out);
}